// round 16
// baseline (speedup 1.0000x reference)
#include <cuda_runtime.h>
#include <cuda_fp16.h>
#include <math.h>
#include <stdint.h>

#define BB  2
#define TT  1024
#define BT  2048
#define DD  1024
#define HH  16
#define CHD 32
#define MHD 64
#define HC  512
#define HM  1024
#define QKV 2048       // fused q|k|v width
#define DE  4096
#define DG  1024
#define EG  5120       // fused exp|gate width
#define LL  6
#define VV  32000
#define EPS 1e-5f

typedef __half h16;
typedef unsigned long long u64;

// ===================== helpers =============================================
__device__ __forceinline__ uint32_t smem_u32(const void* p) {
    uint32_t a;
    asm("{ .reg .u64 t; cvta.to.shared.u64 t, %1; cvt.u32.u64 %0, t; }" : "=r"(a) : "l"(p));
    return a;
}
__device__ __forceinline__ void cp16(uint32_t dst, const void* src) {
    asm volatile("cp.async.cg.shared.global [%0], [%1], 16;" :: "r"(dst), "l"(src));
}
__device__ __forceinline__ void cp_commit() {
    asm volatile("cp.async.commit_group;" ::: "memory");
}
template <int N> __device__ __forceinline__ void cp_wait() {
    asm volatile("cp.async.wait_group %0;" :: "n"(N) : "memory");
}
__device__ __forceinline__ void ldsm_x4(uint32_t& r0, uint32_t& r1, uint32_t& r2,
                                        uint32_t& r3, uint32_t addr) {
    asm volatile("ldmatrix.sync.aligned.m8n8.x4.shared.b16 {%0,%1,%2,%3}, [%4];"
        : "=r"(r0), "=r"(r1), "=r"(r2), "=r"(r3) : "r"(addr));
}
__device__ __forceinline__ void mma16816(float* d, const uint32_t* a, const uint32_t* b) {
    asm volatile("mma.sync.aligned.m16n8k16.row.col.f32.f16.f16.f32 "
        "{%0,%1,%2,%3}, {%4,%5,%6,%7}, {%8,%9}, {%0,%1,%2,%3};"
        : "+f"(d[0]), "+f"(d[1]), "+f"(d[2]), "+f"(d[3])
        : "r"(a[0]), "r"(a[1]), "r"(a[2]), "r"(a[3]), "r"(b[0]), "r"(b[1]));
}
// packed fp32 pair math (Blackwell family f32x2)
#define FMA2(d, a, b) \
    asm("fma.rn.f32x2 %0, %1, %2, %3;" : "=l"(d) : "l"(a), "l"(b), "l"(d))
#define MUL2(d, a, b) \
    asm("mul.rn.f32x2 %0, %1, %2;" : "=l"(d) : "l"(a), "l"(b))

// ===================== scratch =============================================
__device__ float g_x   [BT * DD];
__device__ h16   g_hh  [BT * DD];
__device__ float g_qkv [BT * QKV];
__device__ h16   g_ah  [BT * HM];
__device__ float g_e   [BT * DE];
__device__ h16   g_gh  [BT * DG];
__device__ h16   g_uh  [BT * DE];
__device__ float g_qkvb[LL * QKV];
__device__ float g_egb [LL * EG];
// transposed fp16 weights [L, N, K] (hi only in-network; te keeps hi/lo)
__device__ h16 g_qkvw[LL * QKV * DD];
__device__ h16 g_ow  [LL * DD * HM];
__device__ h16 g_egw [LL * EG * DD];
__device__ h16 g_guw [LL * DE * DG];
__device__ h16 g_cw  [LL * DD * DE];
__device__ h16 g_te_h[VV * DD], g_te_l[VV * DD];

// ===================== conversion kernels ==================================
__device__ __forceinline__ void wsplit_core(
    const float* __restrict__ W, h16* __restrict__ hi,
    int K, int Nin, int nloc, int row_g, int Ntot, int k0, int z) {
    __shared__ float t[64][33];
    W += (size_t)z * K * Nin;
    size_t ob = (size_t)z * Ntot * K;
    int tx = threadIdx.x, ty = threadIdx.y;    // 32 x 8
#pragma unroll
    for (int i = 0; i < 64; i += 8)
        t[ty + i][tx] = W[(size_t)(k0 + ty + i) * Nin + nloc + tx];
    __syncthreads();
#pragma unroll
    for (int i = 0; i < 32; i += 8) {
        int n = ty + i;
        float v0 = t[tx * 2][n], v1 = t[tx * 2 + 1][n];
        size_t o = ob + (size_t)(row_g + n) * K + k0 + tx * 2;
        __half2 hp; hp.x = __float2half(v0); hp.y = __float2half(v1);
        *(__half2*)(hi + o) = hp;
    }
}
__global__ void wsplitT_k(const float* __restrict__ W, h16* __restrict__ hi,
                          int K, int N) {
    wsplit_core(W, hi, K, N, blockIdx.x * 32, blockIdx.x * 32, N,
                blockIdx.y * 64, blockIdx.z);
}
__global__ void wsplit_qkv_k(const float* __restrict__ qw, const float* __restrict__ kw,
                             const float* __restrict__ vw, h16* __restrict__ hi) {
    int n0 = blockIdx.x * 32;
    const float* W; int Nin, nloc;
    if (n0 < HC)           { W = qw; Nin = HC; nloc = n0; }
    else if (n0 < 2 * HC)  { W = kw; Nin = HC; nloc = n0 - HC; }
    else                   { W = vw; Nin = HM; nloc = n0 - 2 * HC; }
    wsplit_core(W, hi, DD, Nin, nloc, n0, QKV, blockIdx.y * 64, blockIdx.z);
}
__global__ void wsplit_eg_k(const float* __restrict__ ew, const float* __restrict__ gw,
                            h16* __restrict__ hi) {
    int n0 = blockIdx.x * 32;
    const float* W; int Nin, nloc;
    if (n0 < DE) { W = ew; Nin = DE; nloc = n0; }
    else         { W = gw; Nin = DG; nloc = n0 - DE; }
    wsplit_core(W, hi, DD, Nin, nloc, n0, EG, blockIdx.y * 64, blockIdx.z);
}
// elementwise hi/lo split (te), 2 elements/thread
__global__ void split_k(const float* __restrict__ W, h16* __restrict__ hi,
                        h16* __restrict__ lo, int n) {
    int i = (blockIdx.x * blockDim.x + threadIdx.x) * 2;
    if (i < n) {
        float2 v = *(const float2*)(W + i);
        __half2 hp, lp;
        hp.x = __float2half(v.x); hp.y = __float2half(v.y);
        lp.x = __float2half(v.x - __half2float(hp.x));
        lp.y = __float2half(v.y - __half2float(hp.y));
        *(__half2*)(hi + i) = hp;
        *(__half2*)(lo + i) = lp;
    }
}

// ===================== embedding + bias concat =============================
__global__ void embed_k(const int* __restrict__ ids, const float* __restrict__ te,
                        const float* __restrict__ pe, float* __restrict__ x,
                        const float* __restrict__ qb, const float* __restrict__ kb,
                        const float* __restrict__ vb, const float* __restrict__ eb,
                        const float* __restrict__ gb, float* __restrict__ qkvb,
                        float* __restrict__ egb) {
    int row = blockIdx.x, t = row % TT, id = ids[row];
    const float* tr = te + (size_t)id * DD;
    const float* pr = pe + (size_t)t  * DD;
    float* xr = x + (size_t)row * DD;
    for (int d = threadIdx.x; d < DD; d += blockDim.x) xr[d] = tr[d] + pr[d];
    if (row < LL) {
        int l = row;
        for (int n = threadIdx.x; n < QKV; n += blockDim.x)
            qkvb[l * QKV + n] = (n < HC) ? qb[l * HC + n]
                              : (n < 2 * HC) ? kb[l * HC + n - HC]
                              : vb[l * HM + n - 2 * HC];
        for (int n = threadIdx.x; n < EG; n += blockDim.x)
            egb[l * EG + n] = (n < DE) ? eb[l * DE + n] : gb[l * DG + n - DE];
    }
}

// ===================== layernorm -> fp16 (shuffle reduction, PDL) ==========
__global__ void ln_k(const float* __restrict__ x, const float* __restrict__ g,
                     const float* __restrict__ b, h16* __restrict__ oh) {
#if __CUDA_ARCH__ >= 900
    cudaGridDependencySynchronize();
#endif
    int row = blockIdx.x;
    const float* xr = x + (size_t)row * DD;
    __shared__ float red[8];
    int tid = threadIdx.x, lane = tid & 31, wid = tid >> 5;

    float s = 0.f;
    for (int d = tid; d < DD; d += 256) s += xr[d];
#pragma unroll
    for (int o = 16; o; o >>= 1) s += __shfl_xor_sync(0xffffffffu, s, o);
    if (lane == 0) red[wid] = s;
    __syncthreads();
    float tot = 0.f;
#pragma unroll
    for (int i = 0; i < 8; i++) tot += red[i];
    float mean = tot * (1.f / DD);
    __syncthreads();

    float v = 0.f;
    for (int d = tid; d < DD; d += 256) { float dv = xr[d] - mean; v += dv * dv; }
#pragma unroll
    for (int o = 16; o; o >>= 1) v += __shfl_xor_sync(0xffffffffu, v, o);
    if (lane == 0) red[wid] = v;
    __syncthreads();
    float vtot = 0.f;
#pragma unroll
    for (int i = 0; i < 8; i++) vtot += red[i];
    float rstd = rsqrtf(vtot * (1.f / DD) + EPS);

    for (int d = tid; d < DD; d += 256) {
        float val = (xr[d] - mean) * rstd * g[d] + b[d];
        oh[(size_t)row * DD + d] = __float2half(val);
    }
}

// ===================== HMMA GEMM (BK=64, SW128; 8 warps 64x32; PDL) ========
// C[M,N] = epi(A @ B^T + bias); A=[M,K] fp16, B=[N,K] fp16.
// PASSES==1: C = A*Bh               (3-stage, in-network)
// PASSES==2: C = A*Bh + A*Bl        (2-stage, logits only)
// Prologue prefetches B (weights, predecessor-independent) BEFORE
// cudaGridDependencySynchronize, then loads A after it.
#define Bb 64
#define MAT_B (128 * 128)           // 16384 B: 128 rows x 128B (64 fp16)
#define SM_SZ (6 * MAT_B)           // 98304 -> 2 CTAs/SM (both configs)

template <int PASSES>
__device__ __forceinline__ void g_loadB(
    uint32_t stg, const h16* __restrict__ Bh, const h16* __restrict__ Bl,
    int n0, int K, int k0, int tid) {
#pragma unroll
    for (int j = 0; j < 4; j++) {
        int c = tid + 256 * j;
        int row = c >> 3, cc = c & 7;
        int pc = cc ^ (row & 7);
        uint32_t so = (uint32_t)(row * 128 + pc * 16);
        size_t gb = (size_t)(n0 + row) * K + k0 + cc * 8;
        cp16(stg + 1 * MAT_B + so, Bh + gb);
        if (PASSES == 2) cp16(stg + 2 * MAT_B + so, Bl + gb);
    }
}
__device__ __forceinline__ void g_loadA(
    uint32_t stg, const h16* __restrict__ Ah, int m0, int K, int k0, int tid) {
#pragma unroll
    for (int j = 0; j < 4; j++) {
        int c = tid + 256 * j;
        int row = c >> 3, cc = c & 7;
        int pc = cc ^ (row & 7);
        uint32_t so = (uint32_t)(row * 128 + pc * 16);
        cp16(stg + so, Ah + (size_t)(m0 + row) * K + k0 + cc * 8);
    }
}
template <int PASSES>
__device__ __forceinline__ void g_load(
    uint32_t stg, const h16* __restrict__ Ah,
    const h16* __restrict__ Bh, const h16* __restrict__ Bl,
    int m0, int n0, int K, int k0, int tid) {
    g_loadA(stg, Ah, m0, K, k0, tid);
    g_loadB<PASSES>(stg, Bh, Bl, n0, K, k0, tid);
}

template <int EPI, int PASSES>
__global__ void __launch_bounds__(256, 2)
hgemm_k(const h16* __restrict__ Ah, const h16* __restrict__ Bh,
        const h16* __restrict__ Bl, const float* __restrict__ bias,
        float* __restrict__ Cf, h16* __restrict__ Ch,
        const float* __restrict__ Ef, int M, int N, int K) {
    constexpr int MATS   = (PASSES == 2) ? 3 : 2;
    constexpr int STAGES = (PASSES == 2) ? 2 : 3;
    constexpr int STG    = MATS * MAT_B;

    extern __shared__ char smem[];
    uint32_t sb = smem_u32(smem);
    int tid = threadIdx.x, lane = tid & 31, wid = tid >> 5;
    int wm = wid >> 2, wn = wid & 3;                 // 2 x 4 warps, 64x32 tiles
    int m0 = blockIdx.y * 128, n0 = blockIdx.x * 128;
    int KS = gridDim.z;
    int Kc = K / KS;
    int kb = blockIdx.z * Kc;

    float acc[4][4][4];
#pragma unroll
    for (int i = 0; i < 4; i++)
#pragma unroll
        for (int j = 0; j < 4; j++)
#pragma unroll
            for (int r = 0; r < 4; r++) acc[i][j][r] = 0.f;

    const int NKI = Kc / Bb;
    // --- B prefetch (weights) BEFORE dependency sync ---
#pragma unroll
    for (int p = 0; p < STAGES - 1; p++)
        g_loadB<PASSES>(sb + p * STG, Bh, Bl, n0, K, kb + p * Bb, tid);
#if __CUDA_ARCH__ >= 900
    cudaGridDependencySynchronize();
#endif
#pragma unroll
    for (int p = 0; p < STAGES - 1; p++) {
        g_loadA(sb + p * STG, Ah, m0, K, kb + p * Bb, tid);
        cp_commit();
    }

    int a_row = lane & 15, a_c = lane >> 4;
    int b_row = ((lane >> 4) << 3) + (lane & 7), b_c = (lane >> 3) & 1;

    for (int it = 0; it < NKI; it++) {
        int s = it % STAGES;
        cp_wait<STAGES - 2>();
        __syncthreads();
        int nk = it + STAGES - 1;
        if (nk < NKI) {
            g_load<PASSES>(sb + (nk % STAGES) * STG, Ah, Bh, Bl, m0, n0, K, kb + nk * Bb, tid);
            cp_commit();
        }

        uint32_t As = sb + s * STG;
        uint32_t Bs_h = As + 1 * MAT_B;
        uint32_t Bs_l = As + 2 * MAT_B;

#pragma unroll
        for (int ks = 0; ks < 4; ks++) {
            uint32_t ah[4][4], bh[2][4], bl[2][4];
#pragma unroll
            for (int mi = 0; mi < 4; mi++) {
                int r = wm * 64 + mi * 16 + a_row;
                int pc = (ks * 2 + a_c) ^ (r & 7);
                ldsm_x4(ah[mi][0], ah[mi][1], ah[mi][2], ah[mi][3],
                        As + (uint32_t)(r * 128 + pc * 16));
            }
#pragma unroll
            for (int np = 0; np < 2; np++) {
                int r = wn * 32 + np * 16 + b_row;
                int pc = (ks * 2 + b_c) ^ (r & 7);
                uint32_t off = (uint32_t)(r * 128 + pc * 16);
                ldsm_x4(bh[np][0], bh[np][1], bh[np][2], bh[np][3], Bs_h + off);
                if (PASSES == 2)
                    ldsm_x4(bl[np][0], bl[np][1], bl[np][2], bl[np][3], Bs_l + off);
            }
#pragma unroll
            for (int mi = 0; mi < 4; mi++)
#pragma unroll
                for (int ni = 0; ni < 4; ni++) {
                    const uint32_t* pbh = &bh[ni >> 1][(ni & 1) * 2];
                    mma16816(acc[mi][ni], ah[mi], pbh);
                    if (PASSES == 2) {
                        const uint32_t* pbl = &bl[ni >> 1][(ni & 1) * 2];
                        mma16816(acc[mi][ni], ah[mi], pbl);
                    }
                }
        }
    }

#if __CUDA_ARCH__ >= 900
    cudaTriggerProgrammaticLaunchCompletion();
#endif

    // -------- epilogue --------
    int g = lane >> 2, t = lane & 3;
#pragma unroll
    for (int mi = 0; mi < 4; mi++) {
#pragma unroll
        for (int ni = 0; ni < 4; ni++) {
#pragma unroll
            for (int hf = 0; hf < 2; hf++) {
                int gm = m0 + wm * 64 + mi * 16 + g + hf * 8;
                int gn = n0 + wn * 32 + ni * 8 + t * 2;
                float v0 = acc[mi][ni][hf * 2 + 0];
                float v1 = acc[mi][ni][hf * 2 + 1];
                if (bias && blockIdx.z == 0) { v0 += bias[gn]; v1 += bias[gn + 1]; }
                if (EPI == 4) {
                    float s0 = 1.f / (1.f + expf(-v0));
                    float s1 = 1.f / (1.f + expf(-v1));
                    const float* er = Ef + (size_t)gm * N + gn;
                    float x0 = er[0] * s0, x1 = er[1] * s1;
                    x0 = x0 / (1.f + expf(-x0));
                    x1 = x1 / (1.f + expf(-x1));
                    __half2 hp; hp.x = __float2half(x0); hp.y = __float2half(x1);
                    *(__half2*)(Ch + (size_t)gm * N + gn) = hp;
                } else if (EPI == 5) {
                    if (gn < DE) {
                        float2 w; w.x = v0; w.y = v1;
                        *(float2*)(Cf + (size_t)gm * DE + gn) = w;
                    } else {
                        v0 = v0 / (1.f + expf(-v0));
                        v1 = v1 / (1.f + expf(-v1));
                        __half2 hp; hp.x = __float2half(v0); hp.y = __float2half(v1);
                        *(__half2*)(Ch + (size_t)gm * DG + gn - DE) = hp;
                    }
                } else {
                    float* cp = Cf + (size_t)gm * N + gn;
                    if (EPI == 1 && KS > 1) {
                        atomicAdd(cp, v0);
                        atomicAdd(cp + 1, v1);
                    } else {
                        if (EPI == 1) { v0 += cp[0]; v1 += cp[1]; }
                        float2 w; w.x = v0; w.y = v1;
                        *(float2*)cp = w;
                    }
                }
            }
        }
    }
}

// ===================== attention: f32x2 packed math (PDL) ==================
#define AQ  128
#define AKT 64
__global__ void __launch_bounds__(128)
attn_k(const float* __restrict__ qkv, h16* __restrict__ oh) {
#if __CUDA_ARCH__ >= 900
    cudaGridDependencySynchronize();
#endif
    __shared__ float ks[AKT][CHD];
    __shared__ float vs[AKT][MHD];
    int q0 = blockIdx.x * AQ, h = blockIdx.y, b = blockIdx.z;
    int tid = threadIdx.x;
    int qg = q0 + tid;

    const float scale = 0.17677669529663689f;
    u64 q2[CHD / 2];
    const float* qr = qkv + (size_t)(b * TT + qg) * QKV + h * CHD;
#pragma unroll
    for (int i = 0; i < CHD / 2; i++) {
        float2 v; v.x = qr[2 * i] * scale; v.y = qr[2 * i + 1] * scale;
        q2[i] = *(u64*)&v;
    }

    float m = -1e30f, l = 0.f;
    u64 acc2[MHD / 2];
    const u64 zz = 0ull;
#pragma unroll
    for (int i = 0; i < MHD / 2; i++) acc2[i] = zz;

    for (int j0 = 0; j0 <= q0 + AQ - AKT; j0 += AKT) {
        __syncthreads();
        for (int idx = tid; idx < AKT * CHD / 4; idx += 128) {
            int r = idx >> 3, c = idx & 7;
            ((float4*)ks)[idx] = *(const float4*)(qkv + (size_t)(b * TT + j0 + r) * QKV + HC + h * CHD + c * 4);
        }
        for (int idx = tid; idx < AKT * MHD / 4; idx += 128) {
            int r = idx >> 4, c = idx & 15;
            ((float4*)vs)[idx] = *(const float4*)(qkv + (size_t)(b * TT + j0 + r) * QKV + 2 * HC + h * MHD + c * 4);
        }
        __syncthreads();

        int jmax = qg - j0 + 1;
        if (jmax > AKT) jmax = AKT;
        for (int jj = 0; jj < jmax; jj++) {
            const u64* k2 = (const u64*)ks[jj];
            u64 s2 = zz;
#pragma unroll
            for (int i = 0; i < CHD / 2; i++) FMA2(s2, q2[i], k2[i]);
            float2 sf = *(float2*)&s2;
            float s = sf.x + sf.y;

            if (s > m) {
                float r = __expf(m - s);
                l *= r;
                float2 rp; rp.x = r; rp.y = r;
                u64 r2 = *(u64*)&rp;
#pragma unroll
                for (int i = 0; i < MHD / 2; i++) MUL2(acc2[i], acc2[i], r2);
                m = s;
            }
            float p = __expf(s - m);
            l += p;
            float2 pp; pp.x = p; pp.y = p;
            u64 p2 = *(u64*)&pp;
            const u64* v2 = (const u64*)vs[jj];
#pragma unroll
            for (int i = 0; i < MHD / 2; i++) FMA2(acc2[i], p2, v2[i]);
        }
    }

    float inv = 1.f / l;
    size_t o = (size_t)(b * TT + qg) * HM + h * MHD;
#pragma unroll
    for (int i = 0; i < MHD / 2; i++) {
        float2 a = *(float2*)&acc2[i];
        __half2 hp;
        hp.x = __float2half(a.x * inv);
        hp.y = __float2half(a.y * inv);
        *(__half2*)(oh + o + 2 * i) = hp;
    }
}

// ===================== host driver =========================================
template <typename F, typename... Args>
static void pdl_launch(F f, dim3 g, dim3 b, size_t sm, Args... args) {
    cudaLaunchConfig_t cfg = {};
    cfg.gridDim = g; cfg.blockDim = b; cfg.dynamicSmemBytes = sm; cfg.stream = 0;
    cudaLaunchAttribute attr[1];
    attr[0].id = cudaLaunchAttributeProgrammaticStreamSerialization;
    attr[0].val.programmaticStreamSerializationAllowed = 1;
    cfg.attrs = attr; cfg.numAttrs = 1;
    cudaLaunchKernelEx(&cfg, f, args...);
}

extern "C" void kernel_launch(void* const* d_in, const int* in_sizes, int n_in,
                              void* d_out, int out_size) {
    const int*   ids    = (const int*)  d_in[0];
    const float* te     = (const float*)d_in[1];
    const float* pe     = (const float*)d_in[2];
    const float* ln1_g  = (const float*)d_in[3];
    const float* ln1_b  = (const float*)d_in[4];
    const float* qp_w   = (const float*)d_in[5];
    const float* qp_b   = (const float*)d_in[6];
    const float* kp_w   = (const float*)d_in[7];
    const float* kp_b   = (const float*)d_in[8];
    const float* vp_w   = (const float*)d_in[9];
    const float* vp_b   = (const float*)d_in[10];
    const float* out_w  = (const float*)d_in[11];
    const float* out_b  = (const float*)d_in[12];
    const float* ln2_g  = (const float*)d_in[13];
    const float* ln2_b  = (const float*)d_in[14];
    const float* exp_w  = (const float*)d_in[15];
    const float* exp_b  = (const float*)d_in[16];
    const float* gate_w = (const float*)d_in[17];
    const float* gate_b = (const float*)d_in[18];
    const float* gup_w  = (const float*)d_in[19];
    const float* gup_b  = (const float*)d_in[20];
    const float* comp_w = (const float*)d_in[21];
    const float* comp_b = (const float*)d_in[22];
    const float* lnf_g  = (const float*)d_in[23];
    const float* lnf_b  = (const float*)d_in[24];
    float* out = (float*)d_out;

    cudaFuncSetAttribute(hgemm_k<0, 1>, cudaFuncAttributeMaxDynamicSharedMemorySize, SM_SZ);
    cudaFuncSetAttribute(hgemm_k<1, 1>, cudaFuncAttributeMaxDynamicSharedMemorySize, SM_SZ);
    cudaFuncSetAttribute(hgemm_k<4, 1>, cudaFuncAttributeMaxDynamicSharedMemorySize, SM_SZ);
    cudaFuncSetAttribute(hgemm_k<5, 1>, cudaFuncAttributeMaxDynamicSharedMemorySize, SM_SZ);
    cudaFuncSetAttribute(hgemm_k<0, 2>, cudaFuncAttributeMaxDynamicSharedMemorySize, SM_SZ);

    float *x, *qkv, *e, *qkvb, *egb;
    h16 *hh, *ah, *gh, *uh;
    h16 *qkvw, *ow, *egw, *guw, *cw, *teh, *tel;
    cudaGetSymbolAddress((void**)&x,    g_x);    cudaGetSymbolAddress((void**)&qkv,  g_qkv);
    cudaGetSymbolAddress((void**)&e,    g_e);
    cudaGetSymbolAddress((void**)&qkvb, g_qkvb); cudaGetSymbolAddress((void**)&egb,  g_egb);
    cudaGetSymbolAddress((void**)&hh,   g_hh);
    cudaGetSymbolAddress((void**)&ah,   g_ah);   cudaGetSymbolAddress((void**)&gh,   g_gh);
    cudaGetSymbolAddress((void**)&uh,   g_uh);
    cudaGetSymbolAddress((void**)&qkvw, g_qkvw); cudaGetSymbolAddress((void**)&ow,   g_ow);
    cudaGetSymbolAddress((void**)&egw,  g_egw);  cudaGetSymbolAddress((void**)&guw,  g_guw);
    cudaGetSymbolAddress((void**)&cw,   g_cw);
    cudaGetSymbolAddress((void**)&teh,  g_te_h); cudaGetSymbolAddress((void**)&tel,  g_te_l);

    dim3 cb(32, 8);
    dim3 gqkv(QKV / 128, BT / 128);
    dim3 geg (EG  / 128, BT / 128);
    dim3 ggu (DE  / 128, BT / 128);
    dim3 go  (DD  / 128, BT / 128, 2);      // split-K
    dim3 glg (VV  / 128, BT / 128);

    // side stream + events (kernel_launch runs only twice: correctness + capture)
    cudaStream_t s1;
    cudaStreamCreateWithFlags(&s1, cudaStreamNonBlocking);
    cudaEvent_t e0, e_ow, e_eg, e_gu, e_cw, e_te;
    cudaEventCreateWithFlags(&e0,   cudaEventDisableTiming);
    cudaEventCreateWithFlags(&e_ow, cudaEventDisableTiming);
    cudaEventCreateWithFlags(&e_eg, cudaEventDisableTiming);
    cudaEventCreateWithFlags(&e_gu, cudaEventDisableTiming);
    cudaEventCreateWithFlags(&e_cw, cudaEventDisableTiming);
    cudaEventCreateWithFlags(&e_te, cudaEventDisableTiming);

    // main stream prologue (launch order keeps process-launch 5 == qkv hgemm)
    embed_k<<<BT, 256>>>(ids, te, pe, x, qp_b, kp_b, vp_b, exp_b, gate_b, qkvb, egb);  // 0
    ln_k<<<BT, 256>>>(x, ln1_g, ln1_b, hh);                                            // 1
    wsplit_qkv_k<<<dim3(QKV / 32, DD / 64, LL), cb>>>(qp_w, kp_w, vp_w, qkvw);         // 2
    hgemm_k<0, 1><<<gqkv, 256, SM_SZ>>>(hh, qkvw, (const h16*)0, qkvb, qkv,
                                        (h16*)0, (const float*)0, BT, QKV, DD);        // 3 <- profiled

    // fork: remaining weight conversions on side stream, overlapped with compute
    cudaEventRecord(e0, 0);
    cudaStreamWaitEvent(s1, e0, 0);
    wsplitT_k<<<dim3(DD / 32, HM / 64, LL), cb, 0, s1>>>(out_w, ow, HM, DD);
    cudaEventRecord(e_ow, s1);
    wsplit_eg_k<<<dim3(EG / 32, DD / 64, LL), cb, 0, s1>>>(exp_w, gate_w, egw);
    cudaEventRecord(e_eg, s1);
    wsplitT_k<<<dim3(DE / 32, DG / 64, LL), cb, 0, s1>>>(gup_w, guw, DG, DE);
    cudaEventRecord(e_gu, s1);
    wsplitT_k<<<dim3(DD / 32, DE / 64, LL), cb, 0, s1>>>(comp_w, cw, DE, DD);
    cudaEventRecord(e_cw, s1);
    split_k<<<(VV * DD / 2 + 255) / 256, 256, 0, s1>>>(te, teh, tel, VV * DD);
    cudaEventRecord(e_te, s1);

    for (int l = 0; l < LL; l++) {
        size_t lqw = (size_t)l * QKV * DD;
        if (l > 0) {
            pdl_launch(ln_k, dim3(BT), dim3(256), 0,
                       (const float*)x, ln1_g + (size_t)l * DD, ln1_b + (size_t)l * DD, hh);
            pdl_launch(hgemm_k<0, 1>, gqkv, dim3(256), (size_t)SM_SZ,
                       (const h16*)hh, (const h16*)(qkvw + lqw), (const h16*)0,
                       (const float*)(qkvb + (size_t)l * QKV), qkv, (h16*)0,
                       (const float*)0, BT, QKV, DD);
        }
        pdl_launch(attn_k, dim3(TT / AQ, HH, BB), dim3(128), 0, (const float*)qkv, ah);
        if (l == 0) cudaStreamWaitEvent(0, e_ow, 0);
        pdl_launch(hgemm_k<1, 1>, go, dim3(256), (size_t)SM_SZ,
                   (const h16*)ah, (const h16*)(ow + (size_t)l * DD * HM), (const h16*)0,
                   (const float*)(out_b + (size_t)l * DD), x, (h16*)0,
                   (const float*)0, BT, DD, HM);
        pdl_launch(ln_k, dim3(BT), dim3(256), 0,
                   (const float*)x, ln2_g + (size_t)l * DD, ln2_b + (size_t)l * DD, hh);
        if (l == 0) cudaStreamWaitEvent(0, e_eg, 0);
        pdl_launch(hgemm_k<5, 1>, geg, dim3(256), (size_t)SM_SZ,
                   (const h16*)hh, (const h16*)(egw + (size_t)l * EG * DD), (const h16*)0,
                   (const float*)(egb + (size_t)l * EG), e, gh,
                   (const float*)0, BT, EG, DD);
        if (l == 0) cudaStreamWaitEvent(0, e_gu, 0);
        pdl_launch(hgemm_k<4, 1>, ggu, dim3(256), (size_t)SM_SZ,
                   (const h16*)gh, (const h16*)(guw + (size_t)l * DE * DG), (const h16*)0,
                   (const float*)(gup_b + (size_t)l * DE), (float*)0, uh,
                   (const float*)e, BT, DE, DG);
        if (l == 0) cudaStreamWaitEvent(0, e_cw, 0);
        pdl_launch(hgemm_k<1, 1>, go, dim3(256), (size_t)SM_SZ,
                   (const h16*)uh, (const h16*)(cw + (size_t)l * DD * DE), (const h16*)0,
                   (const float*)(comp_b + (size_t)l * DD), x, (h16*)0,
                   (const float*)0, BT, DD, DE);
    }

    pdl_launch(ln_k, dim3(BT), dim3(256), 0, (const float*)x, lnf_g, lnf_b, hh);
    cudaStreamWaitEvent(0, e_te, 0);
    pdl_launch(hgemm_k<0, 2>, glg, dim3(256), (size_t)SM_SZ,
               (const h16*)hh, (const h16*)teh, (const h16*)tel,
               (const float*)0, out, (h16*)0, (const float*)0, BT, VV, DD);
}

// round 17
// speedup vs baseline: 1.0968x; 1.0968x over previous
#include <cuda_runtime.h>
#include <cuda_fp16.h>
#include <math.h>
#include <stdint.h>

#define BB  2
#define TT  1024
#define BT  2048
#define DD  1024
#define HH  16
#define CHD 32
#define MHD 64
#define HC  512
#define HM  1024
#define QKV 2048       // fused q|k|v width
#define DE  4096
#define DG  1024
#define EG  5120       // fused exp|gate width
#define LL  6
#define VV  32000
#define EPS 1e-5f

typedef __half h16;
typedef unsigned long long u64;

// ===================== helpers =============================================
__device__ __forceinline__ uint32_t smem_u32(const void* p) {
    uint32_t a;
    asm("{ .reg .u64 t; cvta.to.shared.u64 t, %1; cvt.u32.u64 %0, t; }" : "=r"(a) : "l"(p));
    return a;
}
__device__ __forceinline__ void cp16(uint32_t dst, const void* src) {
    asm volatile("cp.async.cg.shared.global [%0], [%1], 16;" :: "r"(dst), "l"(src));
}
__device__ __forceinline__ void cp_commit() {
    asm volatile("cp.async.commit_group;" ::: "memory");
}
template <int N> __device__ __forceinline__ void cp_wait() {
    asm volatile("cp.async.wait_group %0;" :: "n"(N) : "memory");
}
__device__ __forceinline__ void ldsm_x4(uint32_t& r0, uint32_t& r1, uint32_t& r2,
                                        uint32_t& r3, uint32_t addr) {
    asm volatile("ldmatrix.sync.aligned.m8n8.x4.shared.b16 {%0,%1,%2,%3}, [%4];"
        : "=r"(r0), "=r"(r1), "=r"(r2), "=r"(r3) : "r"(addr));
}
__device__ __forceinline__ void mma16816(float* d, const uint32_t* a, const uint32_t* b) {
    asm volatile("mma.sync.aligned.m16n8k16.row.col.f32.f16.f16.f32 "
        "{%0,%1,%2,%3}, {%4,%5,%6,%7}, {%8,%9}, {%0,%1,%2,%3};"
        : "+f"(d[0]), "+f"(d[1]), "+f"(d[2]), "+f"(d[3])
        : "r"(a[0]), "r"(a[1]), "r"(a[2]), "r"(a[3]), "r"(b[0]), "r"(b[1]));
}
// packed fp32 pair math (Blackwell family f32x2)
#define FMA2(d, a, b) \
    asm("fma.rn.f32x2 %0, %1, %2, %3;" : "=l"(d) : "l"(a), "l"(b), "l"(d))
#define MUL2(d, a, b) \
    asm("mul.rn.f32x2 %0, %1, %2;" : "=l"(d) : "l"(a), "l"(b))

// ===================== scratch =============================================
__device__ float g_x   [BT * DD];
__device__ h16   g_hh  [BT * DD];
__device__ float g_qkv [BT * QKV];
__device__ h16   g_ah  [BT * HM];
__device__ float g_e   [BT * DE];
__device__ h16   g_gh  [BT * DG];
__device__ h16   g_uh  [BT * DE];
__device__ float g_qkvb[LL * QKV];
__device__ float g_egb [LL * EG];
// transposed fp16 weights [L, N, K] (hi only in-network; te keeps hi/lo)
__device__ h16 g_qkvw[LL * QKV * DD];
__device__ h16 g_ow  [LL * DD * HM];
__device__ h16 g_egw [LL * EG * DD];
__device__ h16 g_guw [LL * DE * DG];
__device__ h16 g_cw  [LL * DD * DE];
__device__ h16 g_te_h[VV * DD], g_te_l[VV * DD];

// ===================== conversion kernels ==================================
__device__ __forceinline__ void wsplit_core(
    const float* __restrict__ W, h16* __restrict__ hi,
    int K, int Nin, int nloc, int row_g, int Ntot, int k0, int z) {
    __shared__ float t[64][33];
    W += (size_t)z * K * Nin;
    size_t ob = (size_t)z * Ntot * K;
    int tx = threadIdx.x, ty = threadIdx.y;    // 32 x 8
#pragma unroll
    for (int i = 0; i < 64; i += 8)
        t[ty + i][tx] = W[(size_t)(k0 + ty + i) * Nin + nloc + tx];
    __syncthreads();
#pragma unroll
    for (int i = 0; i < 32; i += 8) {
        int n = ty + i;
        float v0 = t[tx * 2][n], v1 = t[tx * 2 + 1][n];
        size_t o = ob + (size_t)(row_g + n) * K + k0 + tx * 2;
        __half2 hp; hp.x = __float2half(v0); hp.y = __float2half(v1);
        *(__half2*)(hi + o) = hp;
    }
}
__global__ void wsplitT_k(const float* __restrict__ W, h16* __restrict__ hi,
                          int K, int N) {
    wsplit_core(W, hi, K, N, blockIdx.x * 32, blockIdx.x * 32, N,
                blockIdx.y * 64, blockIdx.z);
}
__global__ void wsplit_qkv_k(const float* __restrict__ qw, const float* __restrict__ kw,
                             const float* __restrict__ vw, h16* __restrict__ hi) {
    int n0 = blockIdx.x * 32;
    const float* W; int Nin, nloc;
    if (n0 < HC)           { W = qw; Nin = HC; nloc = n0; }
    else if (n0 < 2 * HC)  { W = kw; Nin = HC; nloc = n0 - HC; }
    else                   { W = vw; Nin = HM; nloc = n0 - 2 * HC; }
    wsplit_core(W, hi, DD, Nin, nloc, n0, QKV, blockIdx.y * 64, blockIdx.z);
}
__global__ void wsplit_eg_k(const float* __restrict__ ew, const float* __restrict__ gw,
                            h16* __restrict__ hi) {
    int n0 = blockIdx.x * 32;
    const float* W; int Nin, nloc;
    if (n0 < DE) { W = ew; Nin = DE; nloc = n0; }
    else         { W = gw; Nin = DG; nloc = n0 - DE; }
    wsplit_core(W, hi, DD, Nin, nloc, n0, EG, blockIdx.y * 64, blockIdx.z);
}
// elementwise hi/lo split (te), 2 elements/thread
__global__ void split_k(const float* __restrict__ W, h16* __restrict__ hi,
                        h16* __restrict__ lo, int n) {
    int i = (blockIdx.x * blockDim.x + threadIdx.x) * 2;
    if (i < n) {
        float2 v = *(const float2*)(W + i);
        __half2 hp, lp;
        hp.x = __float2half(v.x); hp.y = __float2half(v.y);
        lp.x = __float2half(v.x - __half2float(hp.x));
        lp.y = __float2half(v.y - __half2float(hp.y));
        *(__half2*)(hi + i) = hp;
        *(__half2*)(lo + i) = lp;
    }
}

// ===================== embedding + bias concat =============================
__global__ void embed_k(const int* __restrict__ ids, const float* __restrict__ te,
                        const float* __restrict__ pe, float* __restrict__ x,
                        const float* __restrict__ qb, const float* __restrict__ kb,
                        const float* __restrict__ vb, const float* __restrict__ eb,
                        const float* __restrict__ gb, float* __restrict__ qkvb,
                        float* __restrict__ egb) {
    int row = blockIdx.x, t = row % TT, id = ids[row];
    const float* tr = te + (size_t)id * DD;
    const float* pr = pe + (size_t)t  * DD;
    float* xr = x + (size_t)row * DD;
    for (int d = threadIdx.x; d < DD; d += blockDim.x) xr[d] = tr[d] + pr[d];
    if (row < LL) {
        int l = row;
        for (int n = threadIdx.x; n < QKV; n += blockDim.x)
            qkvb[l * QKV + n] = (n < HC) ? qb[l * HC + n]
                              : (n < 2 * HC) ? kb[l * HC + n - HC]
                              : vb[l * HM + n - 2 * HC];
        for (int n = threadIdx.x; n < EG; n += blockDim.x)
            egb[l * EG + n] = (n < DE) ? eb[l * DE + n] : gb[l * DG + n - DE];
    }
}

// ===================== layernorm -> fp16 (shuffle reduction) ===============
__global__ void ln_k(const float* __restrict__ x, const float* __restrict__ g,
                     const float* __restrict__ b, h16* __restrict__ oh) {
    int row = blockIdx.x;
    const float* xr = x + (size_t)row * DD;
    __shared__ float red[8];
    int tid = threadIdx.x, lane = tid & 31, wid = tid >> 5;

    float s = 0.f;
    for (int d = tid; d < DD; d += 256) s += xr[d];
#pragma unroll
    for (int o = 16; o; o >>= 1) s += __shfl_xor_sync(0xffffffffu, s, o);
    if (lane == 0) red[wid] = s;
    __syncthreads();
    float tot = 0.f;
#pragma unroll
    for (int i = 0; i < 8; i++) tot += red[i];
    float mean = tot * (1.f / DD);
    __syncthreads();

    float v = 0.f;
    for (int d = tid; d < DD; d += 256) { float dv = xr[d] - mean; v += dv * dv; }
#pragma unroll
    for (int o = 16; o; o >>= 1) v += __shfl_xor_sync(0xffffffffu, v, o);
    if (lane == 0) red[wid] = v;
    __syncthreads();
    float vtot = 0.f;
#pragma unroll
    for (int i = 0; i < 8; i++) vtot += red[i];
    float rstd = rsqrtf(vtot * (1.f / DD) + EPS);

    for (int d = tid; d < DD; d += 256) {
        float val = (xr[d] - mean) * rstd * g[d] + b[d];
        oh[(size_t)row * DD + d] = __float2half(val);
    }
}

// ===================== HMMA GEMM (BK=64, SW128; 8 warps 64x32) =============
// C[M,N] = epi(A @ B^T + bias); A=[M,K] fp16, B=[N,K] fp16.
// PASSES==1: C = A*Bh               (3-stage, in-network)
// PASSES==2: C = A*Bh + A*Bl        (2-stage, logits only)
// EPI: 0 bias->f32, 1 bias+residual->f32 (atomic when split-K),
//      4 fused sigmoid-gate-silu->h16, 5 fused exp|gate epilogue
#define Bb 64
#define MAT_B (128 * 128)           // 16384 B: 128 rows x 128B (64 fp16)
#define SM_SZ (6 * MAT_B)           // 98304 -> 2 CTAs/SM (both configs)

template <int PASSES>
__device__ __forceinline__ void g_load(
    uint32_t stg, const h16* __restrict__ Ah,
    const h16* __restrict__ Bh, const h16* __restrict__ Bl,
    int m0, int n0, int K, int k0, int tid) {
#pragma unroll
    for (int j = 0; j < 4; j++) {
        int c = tid + 256 * j;              // 0..1023
        int row = c >> 3, cc = c & 7;       // 16B chunk in 128B row
        int pc = cc ^ (row & 7);            // SW128 swizzle
        uint32_t so = (uint32_t)(row * 128 + pc * 16);
        size_t ga = (size_t)(m0 + row) * K + k0 + cc * 8;
        size_t gb = (size_t)(n0 + row) * K + k0 + cc * 8;
        cp16(stg + 0 * MAT_B + so, Ah + ga);
        cp16(stg + 1 * MAT_B + so, Bh + gb);
        if (PASSES == 2) cp16(stg + 2 * MAT_B + so, Bl + gb);
    }
}

template <int EPI, int PASSES>
__global__ void __launch_bounds__(256, 2)
hgemm_k(const h16* __restrict__ Ah, const h16* __restrict__ Bh,
        const h16* __restrict__ Bl, const float* __restrict__ bias,
        float* __restrict__ Cf, h16* __restrict__ Ch,
        const float* __restrict__ Ef, int M, int N, int K) {
    constexpr int MATS   = (PASSES == 2) ? 3 : 2;
    constexpr int STAGES = (PASSES == 2) ? 2 : 3;
    constexpr int STG    = MATS * MAT_B;

    extern __shared__ char smem[];
    uint32_t sb = smem_u32(smem);
    int tid = threadIdx.x, lane = tid & 31, wid = tid >> 5;
    int wm = wid >> 2, wn = wid & 3;                 // 2 x 4 warps, 64x32 tiles
    int m0 = blockIdx.y * 128, n0 = blockIdx.x * 128;
    int KS = gridDim.z;
    int Kc = K / KS;
    int kb = blockIdx.z * Kc;

    float acc[4][4][4];
#pragma unroll
    for (int i = 0; i < 4; i++)
#pragma unroll
        for (int j = 0; j < 4; j++)
#pragma unroll
            for (int r = 0; r < 4; r++) acc[i][j][r] = 0.f;

    const int NKI = Kc / Bb;
#pragma unroll
    for (int p = 0; p < STAGES - 1; p++) {
        g_load<PASSES>(sb + p * STG, Ah, Bh, Bl, m0, n0, K, kb + p * Bb, tid);
        cp_commit();
    }

    int a_row = lane & 15, a_c = lane >> 4;
    int b_row = ((lane >> 4) << 3) + (lane & 7), b_c = (lane >> 3) & 1;

    for (int it = 0; it < NKI; it++) {
        int s = it % STAGES;
        cp_wait<STAGES - 2>();
        __syncthreads();
        int nk = it + STAGES - 1;
        if (nk < NKI) {
            g_load<PASSES>(sb + (nk % STAGES) * STG, Ah, Bh, Bl, m0, n0, K, kb + nk * Bb, tid);
            cp_commit();
        }

        uint32_t As = sb + s * STG;
        uint32_t Bs_h = As + 1 * MAT_B;
        uint32_t Bs_l = As + 2 * MAT_B;

#pragma unroll
        for (int ks = 0; ks < 4; ks++) {
            uint32_t ah[4][4], bh[2][4], bl[2][4];
#pragma unroll
            for (int mi = 0; mi < 4; mi++) {
                int r = wm * 64 + mi * 16 + a_row;
                int pc = (ks * 2 + a_c) ^ (r & 7);
                ldsm_x4(ah[mi][0], ah[mi][1], ah[mi][2], ah[mi][3],
                        As + (uint32_t)(r * 128 + pc * 16));
            }
#pragma unroll
            for (int np = 0; np < 2; np++) {
                int r = wn * 32 + np * 16 + b_row;
                int pc = (ks * 2 + b_c) ^ (r & 7);
                uint32_t off = (uint32_t)(r * 128 + pc * 16);
                ldsm_x4(bh[np][0], bh[np][1], bh[np][2], bh[np][3], Bs_h + off);
                if (PASSES == 2)
                    ldsm_x4(bl[np][0], bl[np][1], bl[np][2], bl[np][3], Bs_l + off);
            }
#pragma unroll
            for (int mi = 0; mi < 4; mi++)
#pragma unroll
                for (int ni = 0; ni < 4; ni++) {
                    const uint32_t* pbh = &bh[ni >> 1][(ni & 1) * 2];
                    mma16816(acc[mi][ni], ah[mi], pbh);
                    if (PASSES == 2) {
                        const uint32_t* pbl = &bl[ni >> 1][(ni & 1) * 2];
                        mma16816(acc[mi][ni], ah[mi], pbl);
                    }
                }
        }
    }

    // -------- epilogue --------
    int g = lane >> 2, t = lane & 3;
#pragma unroll
    for (int mi = 0; mi < 4; mi++) {
#pragma unroll
        for (int ni = 0; ni < 4; ni++) {
#pragma unroll
            for (int hf = 0; hf < 2; hf++) {
                int gm = m0 + wm * 64 + mi * 16 + g + hf * 8;
                int gn = n0 + wn * 32 + ni * 8 + t * 2;
                float v0 = acc[mi][ni][hf * 2 + 0];
                float v1 = acc[mi][ni][hf * 2 + 1];
                if (bias && blockIdx.z == 0) { v0 += bias[gn]; v1 += bias[gn + 1]; }
                if (EPI == 4) {
                    float s0 = 1.f / (1.f + __expf(-v0));
                    float s1 = 1.f / (1.f + __expf(-v1));
                    const float* er = Ef + (size_t)gm * N + gn;
                    float x0 = er[0] * s0, x1 = er[1] * s1;
                    x0 = x0 / (1.f + __expf(-x0));
                    x1 = x1 / (1.f + __expf(-x1));
                    __half2 hp; hp.x = __float2half(x0); hp.y = __float2half(x1);
                    *(__half2*)(Ch + (size_t)gm * N + gn) = hp;
                } else if (EPI == 5) {
                    if (gn < DE) {
                        float2 w; w.x = v0; w.y = v1;
                        *(float2*)(Cf + (size_t)gm * DE + gn) = w;
                    } else {
                        v0 = v0 / (1.f + __expf(-v0));
                        v1 = v1 / (1.f + __expf(-v1));
                        __half2 hp; hp.x = __float2half(v0); hp.y = __float2half(v1);
                        *(__half2*)(Ch + (size_t)gm * DG + gn - DE) = hp;
                    }
                } else {
                    float* cp = Cf + (size_t)gm * N + gn;
                    if (EPI == 1 && KS > 1) {
                        atomicAdd(cp, v0);
                        atomicAdd(cp + 1, v1);
                    } else {
                        if (EPI == 1) { v0 += cp[0]; v1 += cp[1]; }
                        float2 w; w.x = v0; w.y = v1;
                        *(float2*)cp = w;
                    }
                }
            }
        }
    }
}

// ===================== attention: f32x2 packed math ========================
#define AQ  128
#define AKT 64
__global__ void __launch_bounds__(128)
attn_k(const float* __restrict__ qkv, h16* __restrict__ oh) {
    __shared__ float ks[AKT][CHD];
    __shared__ float vs[AKT][MHD];
    int q0 = blockIdx.x * AQ, h = blockIdx.y, b = blockIdx.z;
    int tid = threadIdx.x;
    int qg = q0 + tid;

    const float scale = 0.17677669529663689f;
    u64 q2[CHD / 2];
    const float* qr = qkv + (size_t)(b * TT + qg) * QKV + h * CHD;
#pragma unroll
    for (int i = 0; i < CHD / 2; i++) {
        float2 v; v.x = qr[2 * i] * scale; v.y = qr[2 * i + 1] * scale;
        q2[i] = *(u64*)&v;
    }

    float m = -1e30f, l = 0.f;
    u64 acc2[MHD / 2];
    const u64 zz = 0ull;
#pragma unroll
    for (int i = 0; i < MHD / 2; i++) acc2[i] = zz;

    for (int j0 = 0; j0 <= q0 + AQ - AKT; j0 += AKT) {
        __syncthreads();
        for (int idx = tid; idx < AKT * CHD / 4; idx += 128) {
            int r = idx >> 3, c = idx & 7;
            ((float4*)ks)[idx] = *(const float4*)(qkv + (size_t)(b * TT + j0 + r) * QKV + HC + h * CHD + c * 4);
        }
        for (int idx = tid; idx < AKT * MHD / 4; idx += 128) {
            int r = idx >> 4, c = idx & 15;
            ((float4*)vs)[idx] = *(const float4*)(qkv + (size_t)(b * TT + j0 + r) * QKV + 2 * HC + h * MHD + c * 4);
        }
        __syncthreads();

        int jmax = qg - j0 + 1;
        if (jmax > AKT) jmax = AKT;
        for (int jj = 0; jj < jmax; jj++) {
            const u64* k2 = (const u64*)ks[jj];
            u64 s2 = zz;
#pragma unroll
            for (int i = 0; i < CHD / 2; i++) FMA2(s2, q2[i], k2[i]);
            float2 sf = *(float2*)&s2;
            float s = sf.x + sf.y;

            if (s > m) {
                float r = __expf(m - s);
                l *= r;
                float2 rp; rp.x = r; rp.y = r;
                u64 r2 = *(u64*)&rp;
#pragma unroll
                for (int i = 0; i < MHD / 2; i++) MUL2(acc2[i], acc2[i], r2);
                m = s;
            }
            float p = __expf(s - m);
            l += p;
            float2 pp; pp.x = p; pp.y = p;
            u64 p2 = *(u64*)&pp;
            const u64* v2 = (const u64*)vs[jj];
#pragma unroll
            for (int i = 0; i < MHD / 2; i++) FMA2(acc2[i], p2, v2[i]);
        }
    }

    float inv = 1.f / l;
    size_t o = (size_t)(b * TT + qg) * HM + h * MHD;
#pragma unroll
    for (int i = 0; i < MHD / 2; i++) {
        float2 a = *(float2*)&acc2[i];
        __half2 hp;
        hp.x = __float2half(a.x * inv);
        hp.y = __float2half(a.y * inv);
        *(__half2*)(oh + o + 2 * i) = hp;
    }
}

// ===================== host driver =========================================
extern "C" void kernel_launch(void* const* d_in, const int* in_sizes, int n_in,
                              void* d_out, int out_size) {
    const int*   ids    = (const int*)  d_in[0];
    const float* te     = (const float*)d_in[1];
    const float* pe     = (const float*)d_in[2];
    const float* ln1_g  = (const float*)d_in[3];
    const float* ln1_b  = (const float*)d_in[4];
    const float* qp_w   = (const float*)d_in[5];
    const float* qp_b   = (const float*)d_in[6];
    const float* kp_w   = (const float*)d_in[7];
    const float* kp_b   = (const float*)d_in[8];
    const float* vp_w   = (const float*)d_in[9];
    const float* vp_b   = (const float*)d_in[10];
    const float* out_w  = (const float*)d_in[11];
    const float* out_b  = (const float*)d_in[12];
    const float* ln2_g  = (const float*)d_in[13];
    const float* ln2_b  = (const float*)d_in[14];
    const float* exp_w  = (const float*)d_in[15];
    const float* exp_b  = (const float*)d_in[16];
    const float* gate_w = (const float*)d_in[17];
    const float* gate_b = (const float*)d_in[18];
    const float* gup_w  = (const float*)d_in[19];
    const float* gup_b  = (const float*)d_in[20];
    const float* comp_w = (const float*)d_in[21];
    const float* comp_b = (const float*)d_in[22];
    const float* lnf_g  = (const float*)d_in[23];
    const float* lnf_b  = (const float*)d_in[24];
    float* out = (float*)d_out;

    cudaFuncSetAttribute(hgemm_k<0, 1>, cudaFuncAttributeMaxDynamicSharedMemorySize, SM_SZ);
    cudaFuncSetAttribute(hgemm_k<1, 1>, cudaFuncAttributeMaxDynamicSharedMemorySize, SM_SZ);
    cudaFuncSetAttribute(hgemm_k<4, 1>, cudaFuncAttributeMaxDynamicSharedMemorySize, SM_SZ);
    cudaFuncSetAttribute(hgemm_k<5, 1>, cudaFuncAttributeMaxDynamicSharedMemorySize, SM_SZ);
    cudaFuncSetAttribute(hgemm_k<0, 2>, cudaFuncAttributeMaxDynamicSharedMemorySize, SM_SZ);

    float *x, *qkv, *e, *qkvb, *egb;
    h16 *hh, *ah, *gh, *uh;
    h16 *qkvw, *ow, *egw, *guw, *cw, *teh, *tel;
    cudaGetSymbolAddress((void**)&x,    g_x);    cudaGetSymbolAddress((void**)&qkv,  g_qkv);
    cudaGetSymbolAddress((void**)&e,    g_e);
    cudaGetSymbolAddress((void**)&qkvb, g_qkvb); cudaGetSymbolAddress((void**)&egb,  g_egb);
    cudaGetSymbolAddress((void**)&hh,   g_hh);
    cudaGetSymbolAddress((void**)&ah,   g_ah);   cudaGetSymbolAddress((void**)&gh,   g_gh);
    cudaGetSymbolAddress((void**)&uh,   g_uh);
    cudaGetSymbolAddress((void**)&qkvw, g_qkvw); cudaGetSymbolAddress((void**)&ow,   g_ow);
    cudaGetSymbolAddress((void**)&egw,  g_egw);  cudaGetSymbolAddress((void**)&guw,  g_guw);
    cudaGetSymbolAddress((void**)&cw,   g_cw);
    cudaGetSymbolAddress((void**)&teh,  g_te_h); cudaGetSymbolAddress((void**)&tel,  g_te_l);

    dim3 cb(32, 8);
    dim3 gqkv(QKV / 128, BT / 128);
    dim3 geg (EG  / 128, BT / 128);
    dim3 ggu (DE  / 128, BT / 128);
    dim3 go  (DD  / 128, BT / 128, 2);      // split-K
    dim3 glg (VV  / 128, BT / 128);

    // side stream + events (kernel_launch runs only twice: correctness + capture)
    cudaStream_t s1;
    cudaStreamCreateWithFlags(&s1, cudaStreamNonBlocking);
    cudaEvent_t e0, e_ow, e_eg, e_gu, e_cw, e_te;
    cudaEventCreateWithFlags(&e0,   cudaEventDisableTiming);
    cudaEventCreateWithFlags(&e_ow, cudaEventDisableTiming);
    cudaEventCreateWithFlags(&e_eg, cudaEventDisableTiming);
    cudaEventCreateWithFlags(&e_gu, cudaEventDisableTiming);
    cudaEventCreateWithFlags(&e_cw, cudaEventDisableTiming);
    cudaEventCreateWithFlags(&e_te, cudaEventDisableTiming);

    // main stream prologue (launch order keeps process-launch 5 == qkv hgemm)
    embed_k<<<BT, 256>>>(ids, te, pe, x, qp_b, kp_b, vp_b, exp_b, gate_b, qkvb, egb);  // 0
    ln_k<<<BT, 256>>>(x, ln1_g, ln1_b, hh);                                            // 1
    wsplit_qkv_k<<<dim3(QKV / 32, DD / 64, LL), cb>>>(qp_w, kp_w, vp_w, qkvw);         // 2
    hgemm_k<0, 1><<<gqkv, 256, SM_SZ>>>(hh, qkvw, 0, qkvb, qkv, 0, 0, BT, QKV, DD);    // 3 <- profiled

    // fork: remaining weight conversions on side stream, overlapped with compute
    cudaEventRecord(e0, 0);
    cudaStreamWaitEvent(s1, e0, 0);
    wsplitT_k<<<dim3(DD / 32, HM / 64, LL), cb, 0, s1>>>(out_w, ow, HM, DD);
    cudaEventRecord(e_ow, s1);
    wsplit_eg_k<<<dim3(EG / 32, DD / 64, LL), cb, 0, s1>>>(exp_w, gate_w, egw);
    cudaEventRecord(e_eg, s1);
    wsplitT_k<<<dim3(DE / 32, DG / 64, LL), cb, 0, s1>>>(gup_w, guw, DG, DE);
    cudaEventRecord(e_gu, s1);
    wsplitT_k<<<dim3(DD / 32, DE / 64, LL), cb, 0, s1>>>(comp_w, cw, DE, DD);
    cudaEventRecord(e_cw, s1);
    split_k<<<(VV * DD / 2 + 255) / 256, 256, 0, s1>>>(te, teh, tel, VV * DD);
    cudaEventRecord(e_te, s1);

    for (int l = 0; l < LL; l++) {
        size_t lqw = (size_t)l * QKV * DD;
        if (l > 0) {
            ln_k<<<BT, 256>>>(x, ln1_g + (size_t)l * DD, ln1_b + (size_t)l * DD, hh);
            hgemm_k<0, 1><<<gqkv, 256, SM_SZ>>>(hh, qkvw + lqw, 0,
                                                qkvb + (size_t)l * QKV, qkv, 0, 0, BT, QKV, DD);
        }
        attn_k<<<dim3(TT / AQ, HH, BB), 128>>>(qkv, ah);
        if (l == 0) cudaStreamWaitEvent(0, e_ow, 0);
        hgemm_k<1, 1><<<go, 256, SM_SZ>>>(ah, ow + (size_t)l * DD * HM, 0,
                                          out_b + (size_t)l * DD, x, 0, 0, BT, DD, HM);
        ln_k<<<BT, 256>>>(x, ln2_g + (size_t)l * DD, ln2_b + (size_t)l * DD, hh);
        if (l == 0) cudaStreamWaitEvent(0, e_eg, 0);
        hgemm_k<5, 1><<<geg, 256, SM_SZ>>>(hh, egw + (size_t)l * EG * DD, 0,
                                           egb + (size_t)l * EG, e, gh, 0, BT, EG, DD);
        if (l == 0) cudaStreamWaitEvent(0, e_gu, 0);
        hgemm_k<4, 1><<<ggu, 256, SM_SZ>>>(gh, guw + (size_t)l * DE * DG, 0,
                                           gup_b + (size_t)l * DE, 0, uh, e, BT, DE, DG);
        if (l == 0) cudaStreamWaitEvent(0, e_cw, 0);
        hgemm_k<1, 1><<<go, 256, SM_SZ>>>(uh, cw + (size_t)l * DD * DE, 0,
                                          comp_b + (size_t)l * DD, x, 0, 0, BT, DD, DE);
    }

    ln_k<<<BT, 256>>>(x, lnf_g, lnf_b, hh);
    cudaStreamWaitEvent(0, e_te, 0);
    hgemm_k<0, 2><<<glg, 256, SM_SZ>>>(hh, teh, tel, nullptr, out, 0, 0, BT, VV, DD);
}